// round 2
// baseline (speedup 1.0000x reference)
#include <cuda_runtime.h>
#include <cuda_bf16.h>
#include <cstdint>

#define N_NODES 100000
#define N_EDGES 1600000
#define IN_DIM 128
#define HIDDEN 128
#define OUT_DIM 64

// -------- scratch (static device globals; no allocation allowed) --------
__device__ __align__(16) float g_h[(size_t)N_NODES * HIDDEN];    // x @ W1
__device__ __align__(16) float g_agg[(size_t)N_NODES * HIDDEN];  // scatter accumulator
__device__ float g_dinv[N_NODES];
__device__ int   g_deg[N_NODES];
__device__ int   g_is64;   // 1 if edge_index is int64, 0 if int32

// -------- edge-index dtype detection --------
// int64 indices are < 2^32 (values < 100000). Packed int32 pairs interpreted as
// u64 have nonzero high words w.p. ~1. One block scans 1024 words, ORs high bits.
__global__ void detect_dtype_kernel(const void* __restrict__ ei) {
    __shared__ int any_hi;
    if (threadIdx.x == 0) any_hi = 0;
    __syncthreads();
    const unsigned long long* p = (const unsigned long long*)ei;
    unsigned long long v = p[threadIdx.x];          // 1024 threads
    if ((v >> 32) != 0ULL) atomicOr(&any_hi, 1);
    __syncthreads();
    if (threadIdx.x == 0) g_is64 = any_hi ? 0 : 1;
}

// logical element fetch: src edge e -> elem e ; dst edge e -> elem N_EDGES + e
__device__ __forceinline__ int edge_idx(const void* ei, long long elem, int is64) {
    if (is64) return (int)((const long long*)ei)[elem];
    return ((const int*)ei)[elem];
}

// -------- vector f32 reduction (sm_90+) --------
__device__ __forceinline__ void red_add_v4(float4* addr, float4 v) {
    asm volatile("red.global.add.v4.f32 [%0], {%1, %2, %3, %4};"
                 :: "l"(addr), "f"(v.x), "f"(v.y), "f"(v.z), "f"(v.w)
                 : "memory");
}

// -------- degree kernels --------
__global__ void init_deg_kernel() {
    int i = blockIdx.x * blockDim.x + threadIdx.x;
    if (i < N_NODES) g_deg[i] = 1;  // self-loop
}

__global__ void count_deg_kernel(const void* __restrict__ ei) {
    int e = blockIdx.x * blockDim.x + threadIdx.x;
    if (e < N_EDGES) {
        int d = edge_idx(ei, (long long)N_EDGES + e, g_is64);
        atomicAdd(&g_deg[d], 1);
    }
}

__global__ void dinv_kernel() {
    int i = blockIdx.x * blockDim.x + threadIdx.x;
    if (i < N_NODES) g_dinv[i] = rsqrtf((float)g_deg[i]);
}

// -------- GEMM1: h = x @ W1 ; agg = h * dinv^2 (self-loop init) --------
// block = 256 threads = 8 warps; 16 nodes per block (2 per warp);
// each lane owns 4 contiguous output cols (float4).
__global__ void __launch_bounds__(256) gemm1_kernel(const float* __restrict__ x,
                                                    const float* __restrict__ W1) {
    extern __shared__ float sm[];
    float* Ws = sm;            // 128*128
    float* Xs = sm + 16384;    // 16*128

    int tid = threadIdx.x;
    int base = blockIdx.x * 16;

    // load W1 (4096 float4, 16 per thread, coalesced)
    const float4* W4 = (const float4*)W1;
    float4* Ws4 = (float4*)Ws;
#pragma unroll
    for (int i = 0; i < 16; i++) Ws4[tid + 256 * i] = W4[tid + 256 * i];

    // load 16 rows of x (512 float4, 2 per thread)
    const float4* X4 = (const float4*)(x + (size_t)base * IN_DIM);
    float4* Xs4 = (float4*)Xs;
    Xs4[tid]       = X4[tid];
    Xs4[tid + 256] = X4[tid + 256];
    __syncthreads();

    int warp = tid >> 5, lane = tid & 31;
    const float* x0p = Xs + (2 * warp) * IN_DIM;
    const float* x1p = Xs + (2 * warp + 1) * IN_DIM;

    float4 acc0 = make_float4(0.f, 0.f, 0.f, 0.f);
    float4 acc1 = make_float4(0.f, 0.f, 0.f, 0.f);
#pragma unroll 8
    for (int k = 0; k < IN_DIM; k++) {
        float a0 = x0p[k];
        float a1 = x1p[k];
        float4 w = ((const float4*)(Ws + k * HIDDEN))[lane];
        acc0.x += a0 * w.x; acc0.y += a0 * w.y; acc0.z += a0 * w.z; acc0.w += a0 * w.w;
        acc1.x += a1 * w.x; acc1.y += a1 * w.y; acc1.z += a1 * w.z; acc1.w += a1 * w.w;
    }

    int gn0 = base + 2 * warp;
    int gn1 = gn0 + 1;
    float s0 = g_dinv[gn0]; s0 *= s0;
    float s1 = g_dinv[gn1]; s1 *= s1;

    ((float4*)(g_h + (size_t)gn0 * HIDDEN))[lane] = acc0;
    ((float4*)(g_h + (size_t)gn1 * HIDDEN))[lane] = acc1;
    float4 i0 = make_float4(acc0.x * s0, acc0.y * s0, acc0.z * s0, acc0.w * s0);
    float4 i1 = make_float4(acc1.x * s1, acc1.y * s1, acc1.z * s1, acc1.w * s1);
    ((float4*)(g_agg + (size_t)gn0 * HIDDEN))[lane] = i0;
    ((float4*)(g_agg + (size_t)gn1 * HIDDEN))[lane] = i1;
}

// -------- edge scatter: agg[dst] += h[src] * dinv[src]*dinv[dst] --------
// one warp per edge; each lane handles one float4 (32 lanes * 4 = 128)
__global__ void __launch_bounds__(256) scatter_kernel(const void* __restrict__ ei) {
    int e = blockIdx.x * 8 + (threadIdx.x >> 5);
    if (e >= N_EDGES) return;
    int lane = threadIdx.x & 31;
    int is64 = g_is64;
    int s = edge_idx(ei, e, is64);
    int d = edge_idx(ei, (long long)N_EDGES + e, is64);
    float norm = __ldg(g_dinv + s) * __ldg(g_dinv + d);
    float4 v = ((const float4*)g_h)[(size_t)s * 32 + lane];
    v.x *= norm; v.y *= norm; v.z *= norm; v.w *= norm;
    red_add_v4(((float4*)g_agg) + (size_t)d * 32 + lane, v);
}

// -------- GEMM2: out = relu(agg + b1) @ W2 + b2 --------
// block = 256 threads; 16 nodes per block (2 per warp); each lane owns 2 cols.
__global__ void __launch_bounds__(256) gemm2_kernel(const float* __restrict__ b1,
                                                    const float* __restrict__ W2,
                                                    const float* __restrict__ b2,
                                                    float* __restrict__ out) {
    __shared__ float Ws[HIDDEN * OUT_DIM];  // 32 KB
    __shared__ float Xs[16 * HIDDEN];       // 8 KB

    int tid = threadIdx.x;
    int base = blockIdx.x * 16;

    // load W2 (2048 float4, 8 per thread)
    const float4* W4 = (const float4*)W2;
    float4* Ws4 = (float4*)Ws;
#pragma unroll
    for (int i = 0; i < 8; i++) Ws4[tid + 256 * i] = W4[tid + 256 * i];

    // load 16 rows of agg, apply +b1 and relu (512 float4, 2 per thread)
    const float4* A4 = (const float4*)(g_agg + (size_t)base * HIDDEN);
    const float4* B14 = (const float4*)b1;
    float4* Xs4 = (float4*)Xs;
#pragma unroll
    for (int j = 0; j < 2; j++) {
        int idx = tid + 256 * j;
        float4 v = A4[idx];
        float4 bb = B14[idx & 31];
        v.x = fmaxf(v.x + bb.x, 0.f);
        v.y = fmaxf(v.y + bb.y, 0.f);
        v.z = fmaxf(v.z + bb.z, 0.f);
        v.w = fmaxf(v.w + bb.w, 0.f);
        Xs4[idx] = v;
    }
    __syncthreads();

    int warp = tid >> 5, lane = tid & 31;
    const float* x0p = Xs + (2 * warp) * HIDDEN;
    const float* x1p = Xs + (2 * warp + 1) * HIDDEN;

    float2 acc0 = make_float2(0.f, 0.f);
    float2 acc1 = make_float2(0.f, 0.f);
#pragma unroll 8
    for (int k = 0; k < HIDDEN; k++) {
        float a0 = x0p[k];
        float a1 = x1p[k];
        float2 w = ((const float2*)(Ws + k * OUT_DIM))[lane];
        acc0.x += a0 * w.x; acc0.y += a0 * w.y;
        acc1.x += a1 * w.x; acc1.y += a1 * w.y;
    }

    float2 bb2 = ((const float2*)b2)[lane];
    acc0.x += bb2.x; acc0.y += bb2.y;
    acc1.x += bb2.x; acc1.y += bb2.y;

    int gn0 = base + 2 * warp;
    ((float2*)(out + (size_t)gn0 * OUT_DIM))[lane] = acc0;
    ((float2*)(out + (size_t)(gn0 + 1) * OUT_DIM))[lane] = acc1;
}

extern "C" void kernel_launch(void* const* d_in, const int* in_sizes, int n_in,
                              void* d_out, int out_size) {
    const float* x  = (const float*)d_in[0];
    const float* W1 = (const float*)d_in[1];
    const float* b1 = (const float*)d_in[2];
    const float* W2 = (const float*)d_in[3];
    const float* b2 = (const float*)d_in[4];
    const void*  ei = d_in[5];
    float* out = (float*)d_out;

    // 72 KB dynamic smem for gemm1 (W1 tile + x tile)
    cudaFuncSetAttribute(gemm1_kernel, cudaFuncAttributeMaxDynamicSharedMemorySize, 73728);

    detect_dtype_kernel<<<1, 1024>>>(ei);
    init_deg_kernel<<<(N_NODES + 255) / 256, 256>>>();
    count_deg_kernel<<<(N_EDGES + 255) / 256, 256>>>(ei);
    dinv_kernel<<<(N_NODES + 255) / 256, 256>>>();
    gemm1_kernel<<<N_NODES / 16, 256, 73728>>>(x, W1);
    scatter_kernel<<<N_EDGES / 8, 256>>>(ei);
    gemm2_kernel<<<N_NODES / 16, 256>>>(b1, W2, b2, out);
}

// round 3
// speedup vs baseline: 1.3367x; 1.3367x over previous
#include <cuda_runtime.h>
#include <cuda_bf16.h>
#include <cstdint>

#define N_NODES 100000
#define N_EDGES 1600000
#define IN_DIM 128
#define HIDDEN 128
#define OUT_DIM 64

#define SCAN_BLOCK 512
#define SCAN_NBLK ((N_NODES + SCAN_BLOCK - 1) / SCAN_BLOCK)   // 196

// -------- scratch (static device globals; no allocation allowed) --------
__device__ __align__(16) float g_h[(size_t)N_NODES * HIDDEN];    // x @ W1
__device__ __align__(16) float g_agg[(size_t)N_NODES * HIDDEN];  // aggregated
__device__ float g_dinv[N_NODES];
__device__ int   g_cnt[N_NODES];        // incoming edge count (no self-loop)
__device__ int   g_off[N_NODES];        // CSR exclusive offsets
__device__ int   g_cur[N_NODES];        // bucket cursors
__device__ int   g_blksum[SCAN_NBLK];
__device__ int   g_esrc[N_EDGES];       // src ids grouped by dst
__device__ int   g_is64;                // 1 if edge_index is int64

// -------- edge-index dtype detection --------
__global__ void detect_dtype_kernel(const void* __restrict__ ei) {
    __shared__ int any_hi;
    if (threadIdx.x == 0) any_hi = 0;
    __syncthreads();
    const unsigned long long* p = (const unsigned long long*)ei;
    unsigned long long v = p[threadIdx.x];          // 1024 threads
    if ((v >> 32) != 0ULL) atomicOr(&any_hi, 1);
    __syncthreads();
    if (threadIdx.x == 0) g_is64 = any_hi ? 0 : 1;
}

__device__ __forceinline__ int edge_idx(const void* ei, long long elem, int is64) {
    if (is64) return (int)((const long long*)ei)[elem];
    return ((const int*)ei)[elem];
}

// -------- degree / dinv --------
__global__ void init_cnt_kernel() {
    int i = blockIdx.x * blockDim.x + threadIdx.x;
    if (i < N_NODES) g_cnt[i] = 0;
}

__global__ void count_deg_kernel(const void* __restrict__ ei) {
    int e = blockIdx.x * blockDim.x + threadIdx.x;
    if (e < N_EDGES) {
        int d = edge_idx(ei, (long long)N_EDGES + e, g_is64);
        atomicAdd(&g_cnt[d], 1);
    }
}

__global__ void dinv_kernel() {
    int i = blockIdx.x * blockDim.x + threadIdx.x;
    if (i < N_NODES) g_dinv[i] = rsqrtf((float)(g_cnt[i] + 1));  // +1 self-loop
}

// -------- 3-phase exclusive scan over g_cnt -> g_off --------
__global__ void __launch_bounds__(SCAN_BLOCK) scan1_kernel() {
    __shared__ int sm[SCAN_BLOCK];
    int i = blockIdx.x * SCAN_BLOCK + threadIdx.x;
    int v = (i < N_NODES) ? g_cnt[i] : 0;
    sm[threadIdx.x] = v;
    __syncthreads();
    int val = v;
#pragma unroll
    for (int s = 1; s < SCAN_BLOCK; s <<= 1) {
        int add = (threadIdx.x >= s) ? sm[threadIdx.x - s] : 0;
        __syncthreads();
        val += add;
        sm[threadIdx.x] = val;
        __syncthreads();
    }
    if (i < N_NODES) g_off[i] = val - v;                  // exclusive
    if (threadIdx.x == SCAN_BLOCK - 1) g_blksum[blockIdx.x] = val;
}

__global__ void __launch_bounds__(256) scan2_kernel() {
    __shared__ int sm[256];
    int v = (threadIdx.x < SCAN_NBLK) ? g_blksum[threadIdx.x] : 0;
    sm[threadIdx.x] = v;
    __syncthreads();
    int val = v;
#pragma unroll
    for (int s = 1; s < 256; s <<= 1) {
        int add = (threadIdx.x >= s) ? sm[threadIdx.x - s] : 0;
        __syncthreads();
        val += add;
        sm[threadIdx.x] = val;
        __syncthreads();
    }
    if (threadIdx.x < SCAN_NBLK) g_blksum[threadIdx.x] = val - v;  // exclusive
}

__global__ void scan3_kernel() {
    int i = blockIdx.x * blockDim.x + threadIdx.x;
    if (i < N_NODES) {
        int o = g_off[i] + g_blksum[i / SCAN_BLOCK];
        g_off[i] = o;
        g_cur[i] = o;
    }
}

// -------- bucket edges by dst --------
__global__ void bucket_kernel(const void* __restrict__ ei) {
    int e = blockIdx.x * blockDim.x + threadIdx.x;
    if (e < N_EDGES) {
        int is64 = g_is64;
        int s = edge_idx(ei, e, is64);
        int d = edge_idx(ei, (long long)N_EDGES + e, is64);
        int pos = atomicAdd(&g_cur[d], 1);
        g_esrc[pos] = s;
    }
}

// -------- GEMM1: h = x @ W1 --------
__global__ void __launch_bounds__(256) gemm1_kernel(const float* __restrict__ x,
                                                    const float* __restrict__ W1) {
    extern __shared__ float sm[];
    float* Ws = sm;            // 128*128
    float* Xs = sm + 16384;    // 16*128

    int tid = threadIdx.x;
    int base = blockIdx.x * 16;

    const float4* W4 = (const float4*)W1;
    float4* Ws4 = (float4*)Ws;
#pragma unroll
    for (int i = 0; i < 16; i++) Ws4[tid + 256 * i] = W4[tid + 256 * i];

    const float4* X4 = (const float4*)(x + (size_t)base * IN_DIM);
    float4* Xs4 = (float4*)Xs;
    Xs4[tid]       = X4[tid];
    Xs4[tid + 256] = X4[tid + 256];
    __syncthreads();

    int warp = tid >> 5, lane = tid & 31;
    const float* x0p = Xs + (2 * warp) * IN_DIM;
    const float* x1p = Xs + (2 * warp + 1) * IN_DIM;

    float4 acc0 = make_float4(0.f, 0.f, 0.f, 0.f);
    float4 acc1 = make_float4(0.f, 0.f, 0.f, 0.f);
#pragma unroll 8
    for (int k = 0; k < IN_DIM; k++) {
        float a0 = x0p[k];
        float a1 = x1p[k];
        float4 w = ((const float4*)(Ws + k * HIDDEN))[lane];
        acc0.x += a0 * w.x; acc0.y += a0 * w.y; acc0.z += a0 * w.z; acc0.w += a0 * w.w;
        acc1.x += a1 * w.x; acc1.y += a1 * w.y; acc1.z += a1 * w.z; acc1.w += a1 * w.w;
    }

    int gn0 = base + 2 * warp;
    ((float4*)(g_h + (size_t)gn0 * HIDDEN))[lane] = acc0;
    ((float4*)(g_h + (size_t)(gn0 + 1) * HIDDEN))[lane] = acc1;
}

// -------- aggregate: one warp per dst node over its CSR segment --------
__global__ void __launch_bounds__(256) aggregate_kernel() {
    int node = blockIdx.x * 8 + (threadIdx.x >> 5);
    if (node >= N_NODES) return;
    int lane = threadIdx.x & 31;

    int beg = g_off[node];
    int end = (node + 1 < N_NODES) ? g_off[node + 1] : N_EDGES;
    float dd = g_dinv[node];

    // self-loop: h[node] * dinv^2
    float4 acc = __ldg(((const float4*)g_h) + (size_t)node * 32 + lane);
    float sl = dd * dd;
    acc.x *= sl; acc.y *= sl; acc.z *= sl; acc.w *= sl;

    int i = beg;
    for (; i + 1 < end; i += 2) {
        int s0 = __ldg(g_esrc + i);
        int s1 = __ldg(g_esrc + i + 1);
        float n0 = __ldg(g_dinv + s0) * dd;
        float n1 = __ldg(g_dinv + s1) * dd;
        float4 v0 = __ldg(((const float4*)g_h) + (size_t)s0 * 32 + lane);
        float4 v1 = __ldg(((const float4*)g_h) + (size_t)s1 * 32 + lane);
        acc.x += n0 * v0.x; acc.y += n0 * v0.y; acc.z += n0 * v0.z; acc.w += n0 * v0.w;
        acc.x += n1 * v1.x; acc.y += n1 * v1.y; acc.z += n1 * v1.z; acc.w += n1 * v1.w;
    }
    if (i < end) {
        int s0 = __ldg(g_esrc + i);
        float n0 = __ldg(g_dinv + s0) * dd;
        float4 v0 = __ldg(((const float4*)g_h) + (size_t)s0 * 32 + lane);
        acc.x += n0 * v0.x; acc.y += n0 * v0.y; acc.z += n0 * v0.z; acc.w += n0 * v0.w;
    }

    ((float4*)g_agg)[(size_t)node * 32 + lane] = acc;
}

// -------- GEMM2: out = relu(agg + b1) @ W2 + b2 --------
__global__ void __launch_bounds__(256) gemm2_kernel(const float* __restrict__ b1,
                                                    const float* __restrict__ W2,
                                                    const float* __restrict__ b2,
                                                    float* __restrict__ out) {
    __shared__ float Ws[HIDDEN * OUT_DIM];  // 32 KB
    __shared__ float Xs[16 * HIDDEN];       // 8 KB

    int tid = threadIdx.x;
    int base = blockIdx.x * 16;

    const float4* W4 = (const float4*)W2;
    float4* Ws4 = (float4*)Ws;
#pragma unroll
    for (int i = 0; i < 8; i++) Ws4[tid + 256 * i] = W4[tid + 256 * i];

    const float4* A4 = (const float4*)(g_agg + (size_t)base * HIDDEN);
    const float4* B14 = (const float4*)b1;
    float4* Xs4 = (float4*)Xs;
#pragma unroll
    for (int j = 0; j < 2; j++) {
        int idx = tid + 256 * j;
        float4 v = A4[idx];
        float4 bb = B14[idx & 31];
        v.x = fmaxf(v.x + bb.x, 0.f);
        v.y = fmaxf(v.y + bb.y, 0.f);
        v.z = fmaxf(v.z + bb.z, 0.f);
        v.w = fmaxf(v.w + bb.w, 0.f);
        Xs4[idx] = v;
    }
    __syncthreads();

    int warp = tid >> 5, lane = tid & 31;
    const float* x0p = Xs + (2 * warp) * HIDDEN;
    const float* x1p = Xs + (2 * warp + 1) * HIDDEN;

    float2 acc0 = make_float2(0.f, 0.f);
    float2 acc1 = make_float2(0.f, 0.f);
#pragma unroll 8
    for (int k = 0; k < HIDDEN; k++) {
        float a0 = x0p[k];
        float a1 = x1p[k];
        float2 w = ((const float2*)(Ws + k * OUT_DIM))[lane];
        acc0.x += a0 * w.x; acc0.y += a0 * w.y;
        acc1.x += a1 * w.x; acc1.y += a1 * w.y;
    }

    float2 bb2 = ((const float2*)b2)[lane];
    acc0.x += bb2.x; acc0.y += bb2.y;
    acc1.x += bb2.x; acc1.y += bb2.y;

    int gn0 = base + 2 * warp;
    ((float2*)(out + (size_t)gn0 * OUT_DIM))[lane] = acc0;
    ((float2*)(out + (size_t)(gn0 + 1) * OUT_DIM))[lane] = acc1;
}

extern "C" void kernel_launch(void* const* d_in, const int* in_sizes, int n_in,
                              void* d_out, int out_size) {
    const float* x  = (const float*)d_in[0];
    const float* W1 = (const float*)d_in[1];
    const float* b1 = (const float*)d_in[2];
    const float* W2 = (const float*)d_in[3];
    const float* b2 = (const float*)d_in[4];
    const void*  ei = d_in[5];
    float* out = (float*)d_out;

    cudaFuncSetAttribute(gemm1_kernel, cudaFuncAttributeMaxDynamicSharedMemorySize, 73728);

    detect_dtype_kernel<<<1, 1024>>>(ei);
    init_cnt_kernel<<<(N_NODES + 255) / 256, 256>>>();
    count_deg_kernel<<<(N_EDGES + 255) / 256, 256>>>(ei);
    dinv_kernel<<<(N_NODES + 255) / 256, 256>>>();
    scan1_kernel<<<SCAN_NBLK, SCAN_BLOCK>>>();
    scan2_kernel<<<1, 256>>>();
    scan3_kernel<<<(N_NODES + 255) / 256, 256>>>();
    bucket_kernel<<<(N_EDGES + 255) / 256, 256>>>(ei);
    gemm1_kernel<<<N_NODES / 16, 256, 73728>>>(x, W1);
    aggregate_kernel<<<(N_NODES + 7) / 8, 256>>>();
    gemm2_kernel<<<(N_NODES + 15) / 16, 256>>>(b1, W2, b2, out);
}

// round 4
// speedup vs baseline: 1.5438x; 1.1549x over previous
#include <cuda_runtime.h>
#include <cuda_fp16.h>
#include <cstdint>

#define N_NODES 100000
#define N_PAD   100032          // padded to multiple of 64 for fused gemm tiles
#define N_EDGES 1600000
#define IN_DIM 128
#define HIDDEN 128
#define OUT_DIM 64

#define SCAN_BLOCK 512
#define SCAN_NBLK ((N_NODES + SCAN_BLOCK - 1) / SCAN_BLOCK)   // 196

typedef unsigned long long ull;

// -------- scratch (static device globals; no allocation allowed) --------
__device__ __align__(16) __half g_xh[(size_t)N_NODES * IN_DIM];   // x in fp16
__device__ __align__(16) float g_aggx[(size_t)N_PAD * IN_DIM];    // A_norm @ x
__device__ float g_dinv[N_NODES];
__device__ int   g_cnt[N_NODES];
__device__ int   g_off[N_NODES];
__device__ int   g_cur[N_NODES];
__device__ int   g_blksum[SCAN_NBLK];
__device__ int   g_esrc[N_EDGES];
__device__ int   g_is64;

// -------- packed f32x2 helpers --------
__device__ __forceinline__ void ffma2(ull& d, ull a, ull b) {
    asm("fma.rn.f32x2 %0, %1, %2, %3;" : "=l"(d) : "l"(a), "l"(b), "l"(d));
}
__device__ __forceinline__ ull pack_dup(float v) {
    ull r; asm("mov.b64 %0, {%1, %1};" : "=l"(r) : "f"(v)); return r;
}
__device__ __forceinline__ float2 unpack2(ull v) {
    float2 r; asm("mov.b64 {%0, %1}, %2;" : "=f"(r.x), "=f"(r.y) : "l"(v)); return r;
}

// -------- edge-index dtype detection --------
__global__ void detect_dtype_kernel(const void* __restrict__ ei) {
    __shared__ int any_hi;
    if (threadIdx.x == 0) any_hi = 0;
    __syncthreads();
    const ull* p = (const ull*)ei;
    ull v = p[threadIdx.x];
    if ((v >> 32) != 0ULL) atomicOr(&any_hi, 1);
    __syncthreads();
    if (threadIdx.x == 0) g_is64 = any_hi ? 0 : 1;
}

__device__ __forceinline__ int edge_idx(const void* ei, long long elem, int is64) {
    if (is64) return (int)((const long long*)ei)[elem];
    return ((const int*)ei)[elem];
}

// -------- degree / dinv / scan / bucket --------
__global__ void init_cnt_kernel() {
    int i = blockIdx.x * blockDim.x + threadIdx.x;
    if (i < N_NODES) g_cnt[i] = 0;
}

__global__ void count_deg_kernel(const void* __restrict__ ei) {
    int e = blockIdx.x * blockDim.x + threadIdx.x;
    if (e < N_EDGES) {
        int d = edge_idx(ei, (long long)N_EDGES + e, g_is64);
        atomicAdd(&g_cnt[d], 1);
    }
}

__global__ void dinv_kernel() {
    int i = blockIdx.x * blockDim.x + threadIdx.x;
    if (i < N_NODES) g_dinv[i] = rsqrtf((float)(g_cnt[i] + 1));
}

__global__ void __launch_bounds__(SCAN_BLOCK) scan1_kernel() {
    __shared__ int sm[SCAN_BLOCK];
    int i = blockIdx.x * SCAN_BLOCK + threadIdx.x;
    int v = (i < N_NODES) ? g_cnt[i] : 0;
    sm[threadIdx.x] = v;
    __syncthreads();
    int val = v;
#pragma unroll
    for (int s = 1; s < SCAN_BLOCK; s <<= 1) {
        int add = (threadIdx.x >= s) ? sm[threadIdx.x - s] : 0;
        __syncthreads();
        val += add;
        sm[threadIdx.x] = val;
        __syncthreads();
    }
    if (i < N_NODES) g_off[i] = val - v;
    if (threadIdx.x == SCAN_BLOCK - 1) g_blksum[blockIdx.x] = val;
}

__global__ void __launch_bounds__(256) scan2_kernel() {
    __shared__ int sm[256];
    int v = (threadIdx.x < SCAN_NBLK) ? g_blksum[threadIdx.x] : 0;
    sm[threadIdx.x] = v;
    __syncthreads();
    int val = v;
#pragma unroll
    for (int s = 1; s < 256; s <<= 1) {
        int add = (threadIdx.x >= s) ? sm[threadIdx.x - s] : 0;
        __syncthreads();
        val += add;
        sm[threadIdx.x] = val;
        __syncthreads();
    }
    if (threadIdx.x < SCAN_NBLK) g_blksum[threadIdx.x] = val - v;
}

__global__ void scan3_kernel() {
    int i = blockIdx.x * blockDim.x + threadIdx.x;
    if (i < N_NODES) {
        int o = g_off[i] + g_blksum[i / SCAN_BLOCK];
        g_off[i] = o;
        g_cur[i] = o;
    }
}

__global__ void bucket_kernel(const void* __restrict__ ei) {
    int e = blockIdx.x * blockDim.x + threadIdx.x;
    if (e < N_EDGES) {
        int is64 = g_is64;
        int s = edge_idx(ei, e, is64);
        int d = edge_idx(ei, (long long)N_EDGES + e, is64);
        int pos = atomicAdd(&g_cur[d], 1);
        g_esrc[pos] = s;
    }
}

// -------- convert x to fp16 (4 floats / thread) --------
__global__ void __launch_bounds__(256) convert_kernel(const float* __restrict__ x) {
    int i = blockIdx.x * blockDim.x + threadIdx.x;   // float4 index
    const int total = N_NODES * IN_DIM / 4;
    if (i < total) {
        float4 v = ((const float4*)x)[i];
        uint2 o;
        __half2 h01 = __floats2half2_rn(v.x, v.y);
        __half2 h23 = __floats2half2_rn(v.z, v.w);
        o.x = *(const unsigned int*)&h01;
        o.y = *(const unsigned int*)&h23;
        ((uint2*)g_xh)[i] = o;
    }
}

// -------- aggregate: one warp per dst node, fp16 gather, fp32 accumulate ----
__device__ __forceinline__ void acc_half8(float4& acc, uint2 v, float n) {
    float2 f01 = __half22float2(*(__half2*)&v.x);
    float2 f23 = __half22float2(*(__half2*)&v.y);
    acc.x += n * f01.x; acc.y += n * f01.y;
    acc.z += n * f23.x; acc.w += n * f23.y;
}

__global__ void __launch_bounds__(256) aggregate_kernel() {
    int node = blockIdx.x * 8 + (threadIdx.x >> 5);
    if (node >= N_PAD) return;
    int lane = threadIdx.x & 31;
    float4 acc = make_float4(0.f, 0.f, 0.f, 0.f);

    if (node < N_NODES) {
        int beg = g_off[node];
        int end = (node + 1 < N_NODES) ? g_off[node + 1] : N_EDGES;
        float dd = g_dinv[node];

        // self-loop
        uint2 sv = __ldg(((const uint2*)g_xh) + (size_t)node * 32 + lane);
        acc_half8(acc, sv, dd * dd);

        int i = beg;
        for (; i + 1 < end; i += 2) {
            int s0 = __ldg(g_esrc + i);
            int s1 = __ldg(g_esrc + i + 1);
            float n0 = __ldg(g_dinv + s0) * dd;
            float n1 = __ldg(g_dinv + s1) * dd;
            uint2 v0 = __ldg(((const uint2*)g_xh) + (size_t)s0 * 32 + lane);
            uint2 v1 = __ldg(((const uint2*)g_xh) + (size_t)s1 * 32 + lane);
            acc_half8(acc, v0, n0);
            acc_half8(acc, v1, n1);
        }
        if (i < end) {
            int s0 = __ldg(g_esrc + i);
            float n0 = __ldg(g_dinv + s0) * dd;
            uint2 v0 = __ldg(((const uint2*)g_xh) + (size_t)s0 * 32 + lane);
            acc_half8(acc, v0, n0);
        }
    }
    ((float4*)g_aggx)[(size_t)node * 32 + lane] = acc;
}

// -------- fused GEMM: out = relu(aggx @ W1 + b1) @ W2 + b2 --------
// 512 threads = 16 warps, 64 nodes per block (4 per warp).
// stage1: lane owns 4 cols (2 f32x2 pairs) x 4 nodes.
// stage2: lane owns 2 cols (1 f32x2) x 4 nodes.
// A-operands live in smem dup-packed {a,a} so the mainloop is LDS + FFMA2 only.
__global__ void __launch_bounds__(512) fused_gemm_kernel(const float* __restrict__ b1,
                                                         const float* __restrict__ W1,
                                                         const float* __restrict__ W2,
                                                         const float* __restrict__ b2,
                                                         float* __restrict__ out) {
    extern __shared__ char smraw[];
    float* Ws1 = (float*)smraw;              // 128*128 = 64 KB
    float* Ws2 = Ws1 + 16384;                // 128*64  = 32 KB
    ull*   Xp  = (ull*)(Ws2 + 8192);         // 64 nodes * 128 k, dup-packed = 64 KB
    ull*   Tp  = Xp + 8192;                  // 64 nodes * 128 k, dup-packed = 64 KB

    int tid = threadIdx.x;
    int base = blockIdx.x * 64;

    // load W1 (4096 float4 -> 8/thread) and W2 (2048 float4 -> 4/thread)
    const float4* W14 = (const float4*)W1;
    float4* Ws14 = (float4*)Ws1;
#pragma unroll
    for (int i = 0; i < 8; i++) Ws14[tid + 512 * i] = W14[tid + 512 * i];
    const float4* W24 = (const float4*)W2;
    float4* Ws24 = (float4*)Ws2;
#pragma unroll
    for (int i = 0; i < 4; i++) Ws24[tid + 512 * i] = W24[tid + 512 * i];

    // fill Xp: 64*128 = 8192 values, 16 per thread (4 float4 loads), dup-packed
    {
        const float4* A4 = (const float4*)(g_aggx + (size_t)base * IN_DIM);
#pragma unroll
        for (int i = 0; i < 4; i++) {
            int idx = tid + 512 * i;              // float4 index within tile
            float4 v = A4[idx];
            Xp[idx * 4 + 0] = pack_dup(v.x);
            Xp[idx * 4 + 1] = pack_dup(v.y);
            Xp[idx * 4 + 2] = pack_dup(v.z);
            Xp[idx * 4 + 3] = pack_dup(v.w);
        }
    }
    __syncthreads();

    int warp = tid >> 5, lane = tid & 31;
    int n0 = warp * 4;                        // 4 nodes per warp (tile-local)

    // per-lane biases
    float4 b1v = __ldg(((const float4*)b1) + lane);   // cols 4*lane..+3
    float2 b2v = __ldg(((const float2*)b2) + lane);   // cols 2*lane..+1

    // ---- stage 1: t = relu(aggx @ W1 + b1) ----
    ull acc[4][2];
#pragma unroll
    for (int n = 0; n < 4; n++) { acc[n][0] = 0ULL; acc[n][1] = 0ULL; }

    const ull* xp0 = Xp + (n0 + 0) * 128;
    const ull* xp1 = Xp + (n0 + 1) * 128;
    const ull* xp2 = Xp + (n0 + 2) * 128;
    const ull* xp3 = Xp + (n0 + 3) * 128;

#pragma unroll 8
    for (int k = 0; k < 128; k++) {
        ulonglong2 w = *(const ulonglong2*)(Ws1 + k * 128 + 4 * lane);
        ull a0 = xp0[k], a1 = xp1[k], a2 = xp2[k], a3 = xp3[k];
        ffma2(acc[0][0], a0, w.x); ffma2(acc[0][1], a0, w.y);
        ffma2(acc[1][0], a1, w.x); ffma2(acc[1][1], a1, w.y);
        ffma2(acc[2][0], a2, w.x); ffma2(acc[2][1], a2, w.y);
        ffma2(acc[3][0], a3, w.x); ffma2(acc[3][1], a3, w.y);
    }

    // bias + relu + dup-pack into Tp
#pragma unroll
    for (int n = 0; n < 4; n++) {
        float2 c01 = unpack2(acc[n][0]);
        float2 c23 = unpack2(acc[n][1]);
        float t0 = fmaxf(c01.x + b1v.x, 0.f);
        float t1 = fmaxf(c01.y + b1v.y, 0.f);
        float t2 = fmaxf(c23.x + b1v.z, 0.f);
        float t3 = fmaxf(c23.y + b1v.w, 0.f);
        ull* tp = Tp + (n0 + n) * 128 + 4 * lane;
        tp[0] = pack_dup(t0);
        tp[1] = pack_dup(t1);
        tp[2] = pack_dup(t2);
        tp[3] = pack_dup(t3);
    }
    __syncwarp();   // Tp rows for these nodes written only by this warp

    // ---- stage 2: out = t @ W2 + b2 ----
    ull acc2[4] = {0ULL, 0ULL, 0ULL, 0ULL};
    const ull* tp0 = Tp + (n0 + 0) * 128;
    const ull* tp1 = Tp + (n0 + 1) * 128;
    const ull* tp2 = Tp + (n0 + 2) * 128;
    const ull* tp3 = Tp + (n0 + 3) * 128;

#pragma unroll 8
    for (int k = 0; k < 128; k++) {
        ull w = *(const ull*)(Ws2 + k * 64 + 2 * lane);
        ffma2(acc2[0], tp0[k], w);
        ffma2(acc2[1], tp1[k], w);
        ffma2(acc2[2], tp2[k], w);
        ffma2(acc2[3], tp3[k], w);
    }

#pragma unroll
    for (int n = 0; n < 4; n++) {
        int gnode = base + n0 + n;
        if (gnode < N_NODES) {
            float2 r = unpack2(acc2[n]);
            r.x += b2v.x; r.y += b2v.y;
            ((float2*)(out + (size_t)gnode * OUT_DIM))[lane] = r;
        }
    }
}

extern "C" void kernel_launch(void* const* d_in, const int* in_sizes, int n_in,
                              void* d_out, int out_size) {
    const float* x  = (const float*)d_in[0];
    const float* W1 = (const float*)d_in[1];
    const float* b1 = (const float*)d_in[2];
    const float* W2 = (const float*)d_in[3];
    const float* b2 = (const float*)d_in[4];
    const void*  ei = d_in[5];
    float* out = (float*)d_out;

    const int FUSED_SMEM = 64 * 1024 + 32 * 1024 + 64 * 1024 + 64 * 1024;  // 224 KB
    cudaFuncSetAttribute(fused_gemm_kernel, cudaFuncAttributeMaxDynamicSharedMemorySize, FUSED_SMEM);

    detect_dtype_kernel<<<1, 1024>>>(ei);
    init_cnt_kernel<<<(N_NODES + 255) / 256, 256>>>();
    count_deg_kernel<<<(N_EDGES + 255) / 256, 256>>>(ei);
    dinv_kernel<<<(N_NODES + 255) / 256, 256>>>();
    scan1_kernel<<<SCAN_NBLK, SCAN_BLOCK>>>();
    scan2_kernel<<<1, 256>>>();
    scan3_kernel<<<(N_NODES + 255) / 256, 256>>>();
    bucket_kernel<<<(N_EDGES + 255) / 256, 256>>>(ei);
    convert_kernel<<<(N_NODES * IN_DIM / 4 + 255) / 256, 256>>>(x);
    aggregate_kernel<<<N_PAD / 8, 256>>>();
    fused_gemm_kernel<<<N_PAD / 64, 512, FUSED_SMEM>>>(b1, W1, W2, b2, out);
}

// round 5
// speedup vs baseline: 3.3495x; 2.1697x over previous
#include <cuda_runtime.h>
#include <cuda_fp16.h>
#include <cstdint>

#define N_NODES 100000
#define N_PAD   100096          // multiple of 128 for fused gemm tiles
#define N_EDGES 1600000
#define IN_DIM 128
#define HIDDEN 128
#define OUT_DIM 64

#define SCAN_BLOCK 512
#define SCAN_NBLK ((N_NODES + SCAN_BLOCK - 1) / SCAN_BLOCK)   // 196

typedef unsigned long long ull;
typedef unsigned int u32;

// -------- scratch (static device globals; no allocation allowed) --------
__device__ __align__(16) __half g_xh[(size_t)N_NODES * IN_DIM];   // x in fp16
__device__ __align__(16) __half g_axh[(size_t)N_PAD * IN_DIM];    // A_norm @ x, fp16
__device__ __align__(16) __half g_w1h[IN_DIM * HIDDEN];
__device__ __align__(16) __half g_w2h[HIDDEN * OUT_DIM];
__device__ float g_dinv[N_NODES];
__device__ int   g_cnt[N_NODES];
__device__ int   g_off[N_NODES];
__device__ int   g_cur[N_NODES];
__device__ int   g_blksum[SCAN_NBLK];
__device__ int   g_esrc[N_EDGES];
__device__ int   g_is64;

// -------- mma / ldmatrix helpers --------
#define LDSM4(a0,a1,a2,a3,addr) \
    asm volatile("ldmatrix.sync.aligned.m8n8.x4.shared.b16 {%0,%1,%2,%3},[%4];" \
                 : "=r"(a0),"=r"(a1),"=r"(a2),"=r"(a3) : "r"(addr))
#define LDSM2T(b0,b1,addr) \
    asm volatile("ldmatrix.sync.aligned.m8n8.x2.trans.shared.b16 {%0,%1},[%2];" \
                 : "=r"(b0),"=r"(b1) : "r"(addr))
#define MMA16816(d,a0,a1,a2,a3,b0,b1) \
    asm volatile("mma.sync.aligned.m16n8k16.row.col.f32.f16.f16.f32 " \
                 "{%0,%1,%2,%3},{%4,%5,%6,%7},{%8,%9},{%0,%1,%2,%3};" \
                 : "+f"((d)[0]),"+f"((d)[1]),"+f"((d)[2]),"+f"((d)[3]) \
                 : "r"(a0),"r"(a1),"r"(a2),"r"(a3),"r"(b0),"r"(b1))

__device__ __forceinline__ u32 smaddr(const void* p) {
    return (u32)__cvta_generic_to_shared(p);
}

// -------- edge-index dtype detection --------
__global__ void detect_dtype_kernel(const void* __restrict__ ei) {
    __shared__ int any_hi;
    if (threadIdx.x == 0) any_hi = 0;
    __syncthreads();
    const ull* p = (const ull*)ei;
    ull v = p[threadIdx.x];
    if ((v >> 32) != 0ULL) atomicOr(&any_hi, 1);
    __syncthreads();
    if (threadIdx.x == 0) g_is64 = any_hi ? 0 : 1;
}

__device__ __forceinline__ int edge_idx(const void* ei, long long elem, int is64) {
    if (is64) return (int)((const long long*)ei)[elem];
    return ((const int*)ei)[elem];
}

// -------- degree / scan / bucket --------
__global__ void init_cnt_kernel() {
    int i = blockIdx.x * blockDim.x + threadIdx.x;
    if (i < N_NODES) g_cnt[i] = 0;
}

__global__ void count_deg_kernel(const void* __restrict__ ei) {
    int e = blockIdx.x * blockDim.x + threadIdx.x;
    if (e < N_EDGES) {
        int d = edge_idx(ei, (long long)N_EDGES + e, g_is64);
        atomicAdd(&g_cnt[d], 1);
    }
}

__global__ void __launch_bounds__(SCAN_BLOCK) scan1_kernel() {
    __shared__ int sm[SCAN_BLOCK];
    int i = blockIdx.x * SCAN_BLOCK + threadIdx.x;
    int v = (i < N_NODES) ? g_cnt[i] : 0;
    sm[threadIdx.x] = v;
    __syncthreads();
    int val = v;
#pragma unroll
    for (int s = 1; s < SCAN_BLOCK; s <<= 1) {
        int add = (threadIdx.x >= s) ? sm[threadIdx.x - s] : 0;
        __syncthreads();
        val += add;
        sm[threadIdx.x] = val;
        __syncthreads();
    }
    if (i < N_NODES) g_off[i] = val - v;
    if (threadIdx.x == SCAN_BLOCK - 1) g_blksum[blockIdx.x] = val;
}

__global__ void __launch_bounds__(256) scan2_kernel() {
    __shared__ int sm[256];
    int v = (threadIdx.x < SCAN_NBLK) ? g_blksum[threadIdx.x] : 0;
    sm[threadIdx.x] = v;
    __syncthreads();
    int val = v;
#pragma unroll
    for (int s = 1; s < 256; s <<= 1) {
        int add = (threadIdx.x >= s) ? sm[threadIdx.x - s] : 0;
        __syncthreads();
        val += add;
        sm[threadIdx.x] = val;
        __syncthreads();
    }
    if (threadIdx.x < SCAN_NBLK) g_blksum[threadIdx.x] = val - v;
}

__global__ void scan3_kernel() {
    int i = blockIdx.x * blockDim.x + threadIdx.x;
    if (i < N_NODES) {
        int o = g_off[i] + g_blksum[i / SCAN_BLOCK];
        g_off[i] = o;
        g_cur[i] = o;
        g_dinv[i] = rsqrtf((float)(g_cnt[i] + 1));   // fused dinv (self-loop +1)
    }
}

__global__ void bucket_kernel(const void* __restrict__ ei) {
    int e = blockIdx.x * blockDim.x + threadIdx.x;
    if (e < N_EDGES) {
        int is64 = g_is64;
        int s = edge_idx(ei, e, is64);
        int d = edge_idx(ei, (long long)N_EDGES + e, is64);
        int pos = atomicAdd(&g_cur[d], 1);
        g_esrc[pos] = s;
    }
}

// -------- convert x to fp16 --------
__global__ void __launch_bounds__(256) convert_kernel(const float* __restrict__ x) {
    int i = blockIdx.x * blockDim.x + threadIdx.x;   // float4 index
    const int total = N_NODES * IN_DIM / 4;
    if (i < total) {
        float4 v = ((const float4*)x)[i];
        uint2 o;
        __half2 h01 = __floats2half2_rn(v.x, v.y);
        __half2 h23 = __floats2half2_rn(v.z, v.w);
        o.x = *(const u32*)&h01;
        o.y = *(const u32*)&h23;
        ((uint2*)g_xh)[i] = o;
    }
}

// -------- convert W1, W2 to fp16 --------
__global__ void __launch_bounds__(256) wconvert_kernel(const float* __restrict__ W1,
                                                       const float* __restrict__ W2) {
    int i = blockIdx.x * blockDim.x + threadIdx.x;   // float4 index
    if (i < 4096) {
        float4 v = ((const float4*)W1)[i];
        uint2 o;
        __half2 h01 = __floats2half2_rn(v.x, v.y);
        __half2 h23 = __floats2half2_rn(v.z, v.w);
        o.x = *(const u32*)&h01;
        o.y = *(const u32*)&h23;
        ((uint2*)g_w1h)[i] = o;
    } else if (i < 6144) {
        int j = i - 4096;
        float4 v = ((const float4*)W2)[j];
        uint2 o;
        __half2 h01 = __floats2half2_rn(v.x, v.y);
        __half2 h23 = __floats2half2_rn(v.z, v.w);
        o.x = *(const u32*)&h01;
        o.y = *(const u32*)&h23;
        ((uint2*)g_w2h)[j] = o;
    }
}

// -------- aggregate: one warp per dst node, fp16 gather, fp32 acc, fp16 out --
__device__ __forceinline__ void acc_half8(float4& acc, uint2 v, float n) {
    float2 f01 = __half22float2(*(__half2*)&v.x);
    float2 f23 = __half22float2(*(__half2*)&v.y);
    acc.x += n * f01.x; acc.y += n * f01.y;
    acc.z += n * f23.x; acc.w += n * f23.y;
}

__global__ void __launch_bounds__(256) aggregate_kernel() {
    int node = blockIdx.x * 8 + (threadIdx.x >> 5);
    if (node >= N_PAD) return;
    int lane = threadIdx.x & 31;
    float4 acc = make_float4(0.f, 0.f, 0.f, 0.f);

    if (node < N_NODES) {
        int beg = g_off[node];
        int end = (node + 1 < N_NODES) ? g_off[node + 1] : N_EDGES;
        float dd = g_dinv[node];

        uint2 sv = __ldg(((const uint2*)g_xh) + (size_t)node * 32 + lane);
        acc_half8(acc, sv, dd * dd);   // self-loop

        int i = beg;
        for (; i + 1 < end; i += 2) {
            int s0 = __ldg(g_esrc + i);
            int s1 = __ldg(g_esrc + i + 1);
            float n0 = __ldg(g_dinv + s0) * dd;
            float n1 = __ldg(g_dinv + s1) * dd;
            uint2 v0 = __ldg(((const uint2*)g_xh) + (size_t)s0 * 32 + lane);
            uint2 v1 = __ldg(((const uint2*)g_xh) + (size_t)s1 * 32 + lane);
            acc_half8(acc, v0, n0);
            acc_half8(acc, v1, n1);
        }
        if (i < end) {
            int s0 = __ldg(g_esrc + i);
            float n0 = __ldg(g_dinv + s0) * dd;
            uint2 v0 = __ldg(((const uint2*)g_xh) + (size_t)s0 * 32 + lane);
            acc_half8(acc, v0, n0);
        }
    }
    __half2 h01 = __floats2half2_rn(acc.x, acc.y);
    __half2 h23 = __floats2half2_rn(acc.z, acc.w);
    uint2 o;
    o.x = *(const u32*)&h01;
    o.y = *(const u32*)&h23;
    ((uint2*)g_axh)[(size_t)node * 32 + lane] = o;
}

// -------- fused tensor-core GEMM: out = relu(axh @ W1 + b1) @ W2 + b2 -------
// 512 threads / block, 128 nodes / block.
// stage1: warp (r = w&7, c = w>>3) computes nodes [16r,16r+16) x cols [64c, 64c+64)
// stage2: warp computes nodes [16r,..) x cols [32c, 32c+32)
#define AS 136   // padded row stride (halfs) for 128-wide tiles
#define WS2 72   // padded row stride for 64-wide W2 tile

__global__ void __launch_bounds__(512) fused_mma_kernel(const float* __restrict__ b1,
                                                        const float* __restrict__ b2,
                                                        float* __restrict__ out) {
    extern __shared__ __half smh[];
    __half* sW1 = smh;                 // 128 x AS
    __half* sW2 = sW1 + 128 * AS;      // 128 x WS2
    __half* sA  = sW2 + 128 * WS2;     // 128 x AS
    __half* sT  = sA  + 128 * AS;      // 128 x AS

    int tid = threadIdx.x;
    int base = blockIdx.x * 128;

    // load tiles (16B chunks): W1 2048, A 2048, W2 1024
    {
        const uint4* W14 = (const uint4*)g_w1h;
        const uint4* A4  = (const uint4*)(g_axh + (size_t)base * 128);
#pragma unroll
        for (int i = 0; i < 4; i++) {
            int idx = tid + 512 * i;
            int row = idx >> 4, c = idx & 15;
            *(uint4*)(sW1 + row * AS + c * 8) = W14[idx];
            *(uint4*)(sA  + row * AS + c * 8) = A4[idx];
        }
        const uint4* W24 = (const uint4*)g_w2h;
#pragma unroll
        for (int i = 0; i < 2; i++) {
            int idx = tid + 512 * i;
            int row = idx >> 3, c = idx & 7;
            *(uint4*)(sW2 + row * WS2 + c * 8) = W24[idx];
        }
    }
    __syncthreads();

    int warp = tid >> 5, lane = tid & 31;
    int nr = (warp & 7) * 16;            // node row base
    int colq = 2 * (lane & 3);           // col pair offset within n8 tile
    int rq = lane >> 2;                  // row offset within m16 tile

    // ---- stage 1 ----
    {
        int cb = (warp >> 3) * 64;
        float acc[8][4];
#pragma unroll
        for (int t = 0; t < 8; t++)
#pragma unroll
            for (int j = 0; j < 4; j++) acc[t][j] = 0.f;

        u32 aAbase = smaddr(sA + (nr + (lane & 15)) * AS + ((lane >> 4) * 8));
        u32 aBbase = smaddr(sW1 + (lane & 15) * AS + cb);

#pragma unroll
        for (int ks = 0; ks < 8; ks++) {
            u32 a0, a1, a2, a3;
            LDSM4(a0, a1, a2, a3, aAbase + ks * 32);          // k += 16 halfs
#pragma unroll
            for (int nt = 0; nt < 8; nt++) {
                u32 b0, b1r;
                LDSM2T(b0, b1r, aBbase + ks * 16 * AS * 2 + nt * 16);
                MMA16816(acc[nt], a0, a1, a2, a3, b0, b1r);
            }
        }

        // epilogue: bias + relu -> fp16 T tile
#pragma unroll
        for (int nt = 0; nt < 8; nt++) {
            int c0 = cb + nt * 8 + colq;
            float2 bv = __ldg((const float2*)(b1 + c0));
            int r0 = nr + rq;
            __half2 h0 = __floats2half2_rn(fmaxf(acc[nt][0] + bv.x, 0.f),
                                           fmaxf(acc[nt][1] + bv.y, 0.f));
            __half2 h1 = __floats2half2_rn(fmaxf(acc[nt][2] + bv.x, 0.f),
                                           fmaxf(acc[nt][3] + bv.y, 0.f));
            *(__half2*)(sT + r0 * AS + c0) = h0;
            *(__half2*)(sT + (r0 + 8) * AS + c0) = h1;
        }
    }
    __syncthreads();

    // ---- stage 2 ----
    {
        int cb = (warp >> 3) * 32;
        float acc[4][4];
#pragma unroll
        for (int t = 0; t < 4; t++)
#pragma unroll
            for (int j = 0; j < 4; j++) acc[t][j] = 0.f;

        u32 aAbase = smaddr(sT + (nr + (lane & 15)) * AS + ((lane >> 4) * 8));
        u32 aBbase = smaddr(sW2 + (lane & 15) * WS2 + cb);

#pragma unroll
        for (int ks = 0; ks < 8; ks++) {
            u32 a0, a1, a2, a3;
            LDSM4(a0, a1, a2, a3, aAbase + ks * 32);
#pragma unroll
            for (int nt = 0; nt < 4; nt++) {
                u32 b0, b1r;
                LDSM2T(b0, b1r, aBbase + ks * 16 * WS2 * 2 + nt * 16);
                MMA16816(acc[nt], a0, a1, a2, a3, b0, b1r);
            }
        }

#pragma unroll
        for (int nt = 0; nt < 4; nt++) {
            int c0 = cb + nt * 8 + colq;
            float2 bv = __ldg((const float2*)(b2 + c0));
            int n0 = base + nr + rq;
            int n1 = n0 + 8;
            if (n0 < N_NODES) {
                float2 r = make_float2(acc[nt][0] + bv.x, acc[nt][1] + bv.y);
                *(float2*)(out + (size_t)n0 * OUT_DIM + c0) = r;
            }
            if (n1 < N_NODES) {
                float2 r = make_float2(acc[nt][2] + bv.x, acc[nt][3] + bv.y);
                *(float2*)(out + (size_t)n1 * OUT_DIM + c0) = r;
            }
        }
    }
}

extern "C" void kernel_launch(void* const* d_in, const int* in_sizes, int n_in,
                              void* d_out, int out_size) {
    const float* x  = (const float*)d_in[0];
    const float* W1 = (const float*)d_in[1];
    const float* b1 = (const float*)d_in[2];
    const float* W2 = (const float*)d_in[3];
    const float* b2 = (const float*)d_in[4];
    const void*  ei = d_in[5];
    float* out = (float*)d_out;

    const int FUSED_SMEM = (3 * 128 * AS + 128 * WS2) * 2;   // ~121 KB
    cudaFuncSetAttribute(fused_mma_kernel, cudaFuncAttributeMaxDynamicSharedMemorySize, FUSED_SMEM);

    detect_dtype_kernel<<<1, 1024>>>(ei);
    init_cnt_kernel<<<(N_NODES + 255) / 256, 256>>>();
    count_deg_kernel<<<(N_EDGES + 255) / 256, 256>>>(ei);
    scan1_kernel<<<SCAN_NBLK, SCAN_BLOCK>>>();
    scan2_kernel<<<1, 256>>>();
    scan3_kernel<<<(N_NODES + 255) / 256, 256>>>();
    bucket_kernel<<<(N_EDGES + 255) / 256, 256>>>(ei);
    convert_kernel<<<(N_NODES * IN_DIM / 4 + 255) / 256, 256>>>(x);
    wconvert_kernel<<<24, 256>>>(W1, W2);
    aggregate_kernel<<<N_PAD / 8, 256>>>();
    fused_mma_kernel<<<N_PAD / 128, 512, FUSED_SMEM>>>(b1, b2, out);
}

// round 6
// speedup vs baseline: 3.6315x; 1.0842x over previous
#include <cuda_runtime.h>
#include <cuda_fp16.h>
#include <cstdint>

#define N_NODES 100000
#define N_PAD   100096          // multiple of 128 for fused gemm tiles
#define N_EDGES 1600000
#define IN_DIM 128
#define HIDDEN 128
#define OUT_DIM 64

#define SCAN_TILES 196          // ceil(100000/512)

typedef unsigned long long ull;
typedef unsigned int u32;

// -------- scratch (static device globals; no allocation allowed) --------
__device__ __align__(16) __half g_xh[(size_t)N_NODES * IN_DIM];   // x in fp16
__device__ __align__(16) __half g_axh[(size_t)N_PAD * IN_DIM];    // A_norm @ x, fp16
__device__ __align__(16) __half g_w1h[IN_DIM * HIDDEN];
__device__ __align__(16) __half g_w2h[HIDDEN * OUT_DIM];
__device__ float g_dinv[N_NODES];
// zero blob: [0, N_NODES) = per-node incoming counts ; [N_NODES, +256) = scan status
__device__ int   g_zero_blob[N_NODES + 256];
__device__ int   g_off[N_NODES];
__device__ int   g_cur[N_NODES];
__device__ int   g_esrc[N_EDGES];

#define CNT(i)    (g_zero_blob[i])
#define STATUS(t) (((u32*)g_zero_blob)[N_NODES + (t)])
#define FLAG_AGG 0x40000000u
#define FLAG_INC 0x80000000u
#define VALMASK  0x3FFFFFFFu

// -------- mma / ldmatrix helpers --------
#define LDSM4(a0,a1,a2,a3,addr) \
    asm volatile("ldmatrix.sync.aligned.m8n8.x4.shared.b16 {%0,%1,%2,%3},[%4];" \
                 : "=r"(a0),"=r"(a1),"=r"(a2),"=r"(a3) : "r"(addr))
#define LDSM2T(b0,b1,addr) \
    asm volatile("ldmatrix.sync.aligned.m8n8.x2.trans.shared.b16 {%0,%1},[%2];" \
                 : "=r"(b0),"=r"(b1) : "r"(addr))
#define MMA16816(d,a0,a1,a2,a3,b0,b1) \
    asm volatile("mma.sync.aligned.m16n8k16.row.col.f32.f16.f16.f32 " \
                 "{%0,%1,%2,%3},{%4,%5,%6,%7},{%8,%9},{%0,%1,%2,%3};" \
                 : "+f"((d)[0]),"+f"((d)[1]),"+f"((d)[2]),"+f"((d)[3]) \
                 : "r"(a0),"r"(a1),"r"(a2),"r"(a3),"r"(b0),"r"(b1))

__device__ __forceinline__ u32 smaddr(const void* p) {
    return (u32)__cvta_generic_to_shared(p);
}

__device__ __forceinline__ int edge_idx(const void* ei, long long elem, int is64) {
    if (is64) return (int)((const long long*)ei)[elem];
    return ((const int*)ei)[elem];
}

// block-local edge dtype detection: scan first 256 u64 words; int64 indices have
// zero high words; misread int32 pairs have random-node high halves (P(all 0)~1e-1280)
__device__ __forceinline__ int detect_is64_block(const void* ei) {
    const ull* p = (const ull*)ei;
    int any = __syncthreads_or((int)((p[threadIdx.x & 255] >> 32) != 0ULL));
    return !any;
}

__device__ __forceinline__ void f4_to_h8(float4 v, uint2& o) {
    __half2 h01 = __floats2half2_rn(v.x, v.y);
    __half2 h23 = __floats2half2_rn(v.z, v.w);
    o.x = *(const u32*)&h01;
    o.y = *(const u32*)&h23;
}

// ============ prep (fat kernel): convert x | convert W | count degrees ========
// blocks [0,3125)        : x -> fp16, 4 float4/thread
// blocks [3125,3149)     : W1,W2 -> fp16
// blocks [3149,9399)     : degree count with inline dtype detect
__global__ void __launch_bounds__(256) prep_kernel(const float* __restrict__ x,
                                                   const float* __restrict__ W1,
                                                   const float* __restrict__ W2,
                                                   const void* __restrict__ ei) {
    int b = blockIdx.x, tid = threadIdx.x;
    if (b < 3125) {
        const float4* X4 = (const float4*)x;
#pragma unroll
        for (int j = 0; j < 4; j++) {
            int i = b * 1024 + tid + 256 * j;
            uint2 o; f4_to_h8(X4[i], o);
            ((uint2*)g_xh)[i] = o;
        }
    } else if (b < 3149) {
        int i = (b - 3125) * 256 + tid;          // [0, 6144)
        if (i < 4096) {
            uint2 o; f4_to_h8(((const float4*)W1)[i], o);
            ((uint2*)g_w1h)[i] = o;
        } else {
            int j = i - 4096;                    // [0, 2048)
            uint2 o; f4_to_h8(((const float4*)W2)[j], o);
            ((uint2*)g_w2h)[j] = o;
        }
    } else {
        int is64 = detect_is64_block(ei);
        int e = (b - 3149) * 256 + tid;          // < 1.6M exactly
        int d = edge_idx(ei, (long long)N_EDGES + e, is64);
        atomicAdd(&CNT(d), 1);
    }
}

// ============ single-pass scan (decoupled lookback) + dinv + cur ==============
__device__ __forceinline__ u32 warp_sum_u32(u32 v) {
    v += __shfl_xor_sync(~0u, v, 16);
    v += __shfl_xor_sync(~0u, v, 8);
    v += __shfl_xor_sync(~0u, v, 4);
    v += __shfl_xor_sync(~0u, v, 2);
    v += __shfl_xor_sync(~0u, v, 1);
    return v;
}

__global__ void __launch_bounds__(512) scan_fused_kernel() {
    __shared__ int wsum[16];
    __shared__ int s_prefix;
    int tile = blockIdx.x, tid = threadIdx.x;
    int lane = tid & 31, w = tid >> 5;
    int i = tile * 512 + tid;
    int v = (i < N_NODES) ? CNT(i) : 0;

    // warp inclusive scan
    int xv = v;
#pragma unroll
    for (int d = 1; d < 32; d <<= 1) {
        int y = __shfl_up_sync(~0u, xv, d);
        if (lane >= d) xv += y;
    }
    if (lane == 31) wsum[w] = xv;
    __syncthreads();
    if (w == 0) {
        int s = (lane < 16) ? wsum[lane] : 0;
#pragma unroll
        for (int d = 1; d < 16; d <<= 1) {
            int y = __shfl_up_sync(~0u, s, d);
            if (lane >= d) s += y;
        }
        if (lane < 16) wsum[lane] = s;
    }
    __syncthreads();
    int warp_off = w ? wsum[w - 1] : 0;
    int incl = xv + warp_off;            // inclusive within tile
    int total = wsum[15];

    if (w == 0) {
        if (lane == 0)
            atomicExch(&STATUS(tile), (u32)total | (tile == 0 ? FLAG_INC : FLAG_AGG));
        u32 prefix = 0;
        if (tile > 0) {
            int t = tile - 1;
            while (true) {
                int idx = t - lane;
                u32 s = (idx >= 0) ? atomicAdd(&STATUS(idx), 0u) : FLAG_INC;
                if (__ballot_sync(~0u, (s & 0xC0000000u) != 0u) != 0xFFFFFFFFu) continue;
                u32 incmask = __ballot_sync(~0u, (s & FLAG_INC) != 0u);
                if (incmask == 0u) {
                    prefix += warp_sum_u32(s & VALMASK);
                    t -= 32;
                } else {
                    int firstinc = __ffs(incmask) - 1;
                    u32 contrib = (lane <= firstinc) ? (s & VALMASK) : 0u;
                    prefix += warp_sum_u32(contrib);
                    break;
                }
            }
            if (lane == 0) atomicExch(&STATUS(tile), (prefix + (u32)total) | FLAG_INC);
        }
        if (lane == 0) s_prefix = (int)prefix;
    }
    __syncthreads();
    if (i < N_NODES) {
        int off = s_prefix + incl - v;   // exclusive global
        g_off[i] = off;
        g_cur[i] = off;
        g_dinv[i] = rsqrtf((float)(v + 1));   // +1 self-loop
    }
}

// ============ bucket edges by dst ============
__global__ void __launch_bounds__(256) bucket_kernel(const void* __restrict__ ei) {
    int is64 = detect_is64_block(ei);
    int e = blockIdx.x * 256 + threadIdx.x;   // < 1.6M exactly
    int s = edge_idx(ei, e, is64);
    int d = edge_idx(ei, (long long)N_EDGES + e, is64);
    int pos = atomicAdd(&g_cur[d], 1);
    g_esrc[pos] = s;
}

// ============ aggregate: one warp per dst node, fp16 gather, fp32 acc ========
__device__ __forceinline__ void acc_half8(float4& acc, uint2 v, float n) {
    float2 f01 = __half22float2(*(__half2*)&v.x);
    float2 f23 = __half22float2(*(__half2*)&v.y);
    acc.x += n * f01.x; acc.y += n * f01.y;
    acc.z += n * f23.x; acc.w += n * f23.y;
}

__global__ void __launch_bounds__(256) aggregate_kernel() {
    int node = blockIdx.x * 8 + (threadIdx.x >> 5);
    if (node >= N_PAD) return;
    int lane = threadIdx.x & 31;
    float4 acc = make_float4(0.f, 0.f, 0.f, 0.f);

    if (node < N_NODES) {
        int beg = g_off[node];
        int end = (node + 1 < N_NODES) ? g_off[node + 1] : N_EDGES;
        float dd = g_dinv[node];

        uint2 sv = __ldg(((const uint2*)g_xh) + (size_t)node * 32 + lane);
        acc_half8(acc, sv, dd * dd);   // self-loop

        int i = beg;
        for (; i + 3 < end; i += 4) {
            int s0 = __ldg(g_esrc + i);
            int s1 = __ldg(g_esrc + i + 1);
            int s2 = __ldg(g_esrc + i + 2);
            int s3 = __ldg(g_esrc + i + 3);
            float n0 = __ldg(g_dinv + s0) * dd;
            float n1 = __ldg(g_dinv + s1) * dd;
            float n2 = __ldg(g_dinv + s2) * dd;
            float n3 = __ldg(g_dinv + s3) * dd;
            uint2 v0 = __ldg(((const uint2*)g_xh) + (size_t)s0 * 32 + lane);
            uint2 v1 = __ldg(((const uint2*)g_xh) + (size_t)s1 * 32 + lane);
            uint2 v2 = __ldg(((const uint2*)g_xh) + (size_t)s2 * 32 + lane);
            uint2 v3 = __ldg(((const uint2*)g_xh) + (size_t)s3 * 32 + lane);
            acc_half8(acc, v0, n0);
            acc_half8(acc, v1, n1);
            acc_half8(acc, v2, n2);
            acc_half8(acc, v3, n3);
        }
        for (; i < end; i++) {
            int s0 = __ldg(g_esrc + i);
            float n0 = __ldg(g_dinv + s0) * dd;
            uint2 v0 = __ldg(((const uint2*)g_xh) + (size_t)s0 * 32 + lane);
            acc_half8(acc, v0, n0);
        }
    }
    __half2 h01 = __floats2half2_rn(acc.x, acc.y);
    __half2 h23 = __floats2half2_rn(acc.z, acc.w);
    uint2 o;
    o.x = *(const u32*)&h01;
    o.y = *(const u32*)&h23;
    ((uint2*)g_axh)[(size_t)node * 32 + lane] = o;
}

// -------- fused tensor-core GEMM: out = relu(axh @ W1 + b1) @ W2 + b2 -------
#define AS 136   // padded row stride (halfs) for 128-wide tiles
#define WS2 72   // padded row stride for 64-wide W2 tile

__global__ void __launch_bounds__(512) fused_mma_kernel(const float* __restrict__ b1,
                                                        const float* __restrict__ b2,
                                                        float* __restrict__ out) {
    extern __shared__ __half smh[];
    __half* sW1 = smh;                 // 128 x AS
    __half* sW2 = sW1 + 128 * AS;      // 128 x WS2
    __half* sA  = sW2 + 128 * WS2;     // 128 x AS
    __half* sT  = sA  + 128 * AS;      // 128 x AS

    int tid = threadIdx.x;
    int base = blockIdx.x * 128;

    {
        const uint4* W14 = (const uint4*)g_w1h;
        const uint4* A4  = (const uint4*)(g_axh + (size_t)base * 128);
#pragma unroll
        for (int i = 0; i < 4; i++) {
            int idx = tid + 512 * i;
            int row = idx >> 4, c = idx & 15;
            *(uint4*)(sW1 + row * AS + c * 8) = W14[idx];
            *(uint4*)(sA  + row * AS + c * 8) = A4[idx];
        }
        const uint4* W24 = (const uint4*)g_w2h;
#pragma unroll
        for (int i = 0; i < 2; i++) {
            int idx = tid + 512 * i;
            int row = idx >> 3, c = idx & 7;
            *(uint4*)(sW2 + row * WS2 + c * 8) = W24[idx];
        }
    }
    __syncthreads();

    int warp = tid >> 5, lane = tid & 31;
    int nr = (warp & 7) * 16;
    int colq = 2 * (lane & 3);
    int rq = lane >> 2;

    // ---- stage 1 ----
    {
        int cb = (warp >> 3) * 64;
        float acc[8][4];
#pragma unroll
        for (int t = 0; t < 8; t++)
#pragma unroll
            for (int j = 0; j < 4; j++) acc[t][j] = 0.f;

        u32 aAbase = smaddr(sA + (nr + (lane & 15)) * AS + ((lane >> 4) * 8));
        u32 aBbase = smaddr(sW1 + (lane & 15) * AS + cb);

#pragma unroll
        for (int ks = 0; ks < 8; ks++) {
            u32 a0, a1, a2, a3;
            LDSM4(a0, a1, a2, a3, aAbase + ks * 32);
#pragma unroll
            for (int nt = 0; nt < 8; nt++) {
                u32 b0, b1r;
                LDSM2T(b0, b1r, aBbase + ks * 16 * AS * 2 + nt * 16);
                MMA16816(acc[nt], a0, a1, a2, a3, b0, b1r);
            }
        }

#pragma unroll
        for (int nt = 0; nt < 8; nt++) {
            int c0 = cb + nt * 8 + colq;
            float2 bv = __ldg((const float2*)(b1 + c0));
            int r0 = nr + rq;
            __half2 h0 = __floats2half2_rn(fmaxf(acc[nt][0] + bv.x, 0.f),
                                           fmaxf(acc[nt][1] + bv.y, 0.f));
            __half2 h1 = __floats2half2_rn(fmaxf(acc[nt][2] + bv.x, 0.f),
                                           fmaxf(acc[nt][3] + bv.y, 0.f));
            *(__half2*)(sT + r0 * AS + c0) = h0;
            *(__half2*)(sT + (r0 + 8) * AS + c0) = h1;
        }
    }
    __syncthreads();

    // ---- stage 2 ----
    {
        int cb = (warp >> 3) * 32;
        float acc[4][4];
#pragma unroll
        for (int t = 0; t < 4; t++)
#pragma unroll
            for (int j = 0; j < 4; j++) acc[t][j] = 0.f;

        u32 aAbase = smaddr(sT + (nr + (lane & 15)) * AS + ((lane >> 4) * 8));
        u32 aBbase = smaddr(sW2 + (lane & 15) * WS2 + cb);

#pragma unroll
        for (int ks = 0; ks < 8; ks++) {
            u32 a0, a1, a2, a3;
            LDSM4(a0, a1, a2, a3, aAbase + ks * 32);
#pragma unroll
            for (int nt = 0; nt < 4; nt++) {
                u32 b0, b1r;
                LDSM2T(b0, b1r, aBbase + ks * 16 * WS2 * 2 + nt * 16);
                MMA16816(acc[nt], a0, a1, a2, a3, b0, b1r);
            }
        }

#pragma unroll
        for (int nt = 0; nt < 4; nt++) {
            int c0 = cb + nt * 8 + colq;
            float2 bv = __ldg((const float2*)(b2 + c0));
            int n0 = base + nr + rq;
            int n1 = n0 + 8;
            if (n0 < N_NODES) {
                float2 r = make_float2(acc[nt][0] + bv.x, acc[nt][1] + bv.y);
                *(float2*)(out + (size_t)n0 * OUT_DIM + c0) = r;
            }
            if (n1 < N_NODES) {
                float2 r = make_float2(acc[nt][2] + bv.x, acc[nt][3] + bv.y);
                *(float2*)(out + (size_t)n1 * OUT_DIM + c0) = r;
            }
        }
    }
}

extern "C" void kernel_launch(void* const* d_in, const int* in_sizes, int n_in,
                              void* d_out, int out_size) {
    const float* x  = (const float*)d_in[0];
    const float* W1 = (const float*)d_in[1];
    const float* b1 = (const float*)d_in[2];
    const float* W2 = (const float*)d_in[3];
    const float* b2 = (const float*)d_in[4];
    const void*  ei = d_in[5];
    float* out = (float*)d_out;

    const int FUSED_SMEM = (3 * 128 * AS + 128 * WS2) * 2;   // ~121 KB
    cudaFuncSetAttribute(fused_mma_kernel, cudaFuncAttributeMaxDynamicSharedMemorySize, FUSED_SMEM);

    void* zero_ptr = nullptr;
    cudaGetSymbolAddress(&zero_ptr, g_zero_blob);
    cudaMemsetAsync(zero_ptr, 0, (N_NODES + 256) * sizeof(int));

    prep_kernel<<<3125 + 24 + 6250, 256>>>(x, W1, W2, ei);
    scan_fused_kernel<<<SCAN_TILES, 512>>>();
    bucket_kernel<<<N_EDGES / 256, 256>>>(ei);
    aggregate_kernel<<<N_PAD / 8, 256>>>();
    fused_mma_kernel<<<N_PAD / 128, 512, FUSED_SMEM>>>(b1, b2, out);
}